// round 2
// baseline (speedup 1.0000x reference)
#include <cuda_runtime.h>
#include <cuda_bf16.h>
#include <cstdint>

// Problem constants
#define BS_ROWS 4096      // B*S
#define NHEAD   8
#define DIM     64        // d == D_head
#define NLAND   2048      // landmarks per head
#define DOUT    512
#define ALPHA_C 0.5f
#define BETA_C  0.5f
#define EPS_C   1e-12f

// Scratch (device globals: no allocation allowed)
__device__ float g_R2[NHEAD * NLAND];
__device__ float g_qa[NHEAD * NLAND];
__device__ float g_y [BS_ROWS * DOUT];   // 8 MB intermediate y = concat_h y_h

// ---------------------------------------------------------------------------
// Kernel 0: precompute per-landmark ||R||^2 and qpos^(-alpha)
// ---------------------------------------------------------------------------
__global__ void prep_kernel(const float* __restrict__ R, const float* __restrict__ q)
{
    int idx = blockIdx.x * blockDim.x + threadIdx.x;   // h*NLAND + n
    if (idx < NHEAD * NLAND) {
        const float* r = R + (size_t)idx * DIM;
        float s = 0.f;
        #pragma unroll 16
        for (int k = 0; k < DIM; k++) s += r[k] * r[k];
        g_R2[idx] = s;
        float qq = q[idx];
        qq = (qq > 0.f ? qq : 0.f) + EPS_C;
        g_qa[idx] = rsqrtf(qq);                        // qpos^(-0.5)
    }
}

// ---------------------------------------------------------------------------
// Kernel 1: fused  K -> normalize -> P@W  per (head, 64-row tile)
//   block: 256 threads (16x16), BM=64 rows, BN=64 landmarks per tile
//   smem: sZt [64][68] (z transposed, [k][i])
//         sRt [64][68] (R tile transposed, [k][j]) -- ALIASED with sKt [j][i]
//   GEMM2 reads W straight from gmem (L1/L2 resident, 16 KB/tile)
// ---------------------------------------------------------------------------
#define BM 64
#define BN 64
#define LDA 68   // padded stride (floats): conflict-free float4 reads, 4-way stores

__global__ void __launch_bounds__(256)
fused_kernel(const float* __restrict__ z, const float* __restrict__ R,
             const float* __restrict__ W)
{
    __shared__ float sZt[DIM * LDA];      // [k][i]
    __shared__ float sRt[BN * LDA];       // [k][j], aliased as sKt[j][i]
    __shared__ float sZ2[BM];
    __shared__ float sR2[BN];
    __shared__ float sQa[BN];
    __shared__ float sScale[BM];

    float* sKt = sRt;                      // alias (sequenced by syncthreads)

    const int h    = blockIdx.y;
    const int row0 = blockIdx.x * BM;
    const int tid  = threadIdx.x;
    const int tx   = tid & 15;             // 0..15 -> landmark/dh quad
    const int ty   = tid >> 4;             // 0..15 -> row quad

    // ---- load z tile transposed: sZt[k][i] = z[row0+i, h, k] ----
    for (int t = tid; t < BM * DIM; t += 256) {
        int i = t >> 6, k = t & 63;
        sZt[k * LDA + i] = z[((size_t)(row0 + i) * NHEAD + h) * DIM + k];
    }
    __syncthreads();

    // ---- per-row squared norms ----
    if (tid < BM) {
        float s = 0.f;
        #pragma unroll 8
        for (int k = 0; k < DIM; k++) { float v = sZt[k * LDA + tid]; s += v * v; }
        sZ2[tid] = s;
    }

    float acc[4][4];                       // y accumulator: rows 4ty.., dh 4tx..
    float p1[4], p2[4];                    // per-row sum K, sum Kt (partial)
    #pragma unroll
    for (int r = 0; r < 4; r++) {
        p1[r] = 0.f; p2[r] = 0.f;
        #pragma unroll
        for (int c = 0; c < 4; c++) acc[r][c] = 0.f;
    }

    const float* Rh  = R + (size_t)h * NLAND * DIM;
    const float* Wh  = W + (size_t)h * NLAND * DIM;
    const float* R2h = g_R2 + h * NLAND;
    const float* Qah = g_qa + h * NLAND;

    for (int n0 = 0; n0 < NLAND; n0 += BN) {
        __syncthreads();   // previous tile's sKt readers done before overwriting sRt

        // ---- load R tile transposed: sRt[k][j] = R[h, n0+j, k] ----
        for (int t = tid; t < BN * DIM; t += 256) {
            int j = t >> 6, k = t & 63;
            sRt[k * LDA + j] = Rh[(size_t)(n0 + j) * DIM + k];
        }
        if (tid < BN) { sR2[tid] = R2h[n0 + tid]; sQa[tid] = Qah[n0 + tid]; }
        __syncthreads();

        // ---- GEMM1: S[i][j] = sum_k z[i][k] * R[j][k] ----
        float S[4][4];
        #pragma unroll
        for (int r = 0; r < 4; r++)
            #pragma unroll
            for (int c = 0; c < 4; c++) S[r][c] = 0.f;

        #pragma unroll 8
        for (int k = 0; k < DIM; k++) {
            float4 a = *reinterpret_cast<const float4*>(&sZt[k * LDA + 4 * ty]);
            float4 b = *reinterpret_cast<const float4*>(&sRt[k * LDA + 4 * tx]);
            float av[4] = {a.x, a.y, a.z, a.w};
            float bv[4] = {b.x, b.y, b.z, b.w};
            #pragma unroll
            for (int r = 0; r < 4; r++)
                #pragma unroll
                for (int c = 0; c < 4; c++) S[r][c] += av[r] * bv[c];
        }

        // ---- elementwise: dist2 -> K -> Kt; accumulate row sums ----
        float z2v[4], r2v[4], qav[4];
        #pragma unroll
        for (int r = 0; r < 4; r++) z2v[r] = sZ2[4 * ty + r];
        #pragma unroll
        for (int c = 0; c < 4; c++) { r2v[c] = sR2[4 * tx + c]; qav[c] = sQa[4 * tx + c]; }

        float Kt[4][4];
        #pragma unroll
        for (int r = 0; r < 4; r++) {
            #pragma unroll
            for (int c = 0; c < 4; c++) {
                float d2 = z2v[r] - 2.f * S[r][c] + r2v[c];
                d2 = fmaxf(d2, 0.f);
                float K = __expf(-BETA_C * d2);
                p1[r] += K;
                float kt = K * qav[c];
                p2[r] += kt;
                Kt[r][c] = kt;
            }
        }

        __syncthreads();   // all GEMM1 reads of sRt complete

        // ---- store Kt transposed into aliased buffer: sKt[j][i] ----
        #pragma unroll
        for (int c = 0; c < 4; c++) {
            float4 v = make_float4(Kt[0][c], Kt[1][c], Kt[2][c], Kt[3][c]);
            *reinterpret_cast<float4*>(&sKt[(4 * tx + c) * LDA + 4 * ty]) = v;
        }
        __syncthreads();

        // ---- GEMM2: acc[i][dh] += sum_j Kt[i][j] * W[n0+j][dh] ----
        // W read directly from gmem (16 KB/tile, L1/L2 resident)
        #pragma unroll 4
        for (int j = 0; j < BN; j++) {
            float4 a = *reinterpret_cast<const float4*>(&sKt[j * LDA + 4 * ty]);
            float4 b = *reinterpret_cast<const float4*>(&Wh[(size_t)(n0 + j) * DIM + 4 * tx]);
            float av[4] = {a.x, a.y, a.z, a.w};
            float bv[4] = {b.x, b.y, b.z, b.w};
            #pragma unroll
            for (int r = 0; r < 4; r++)
                #pragma unroll
                for (int c = 0; c < 4; c++) acc[r][c] += av[r] * bv[c];
        }
    }

    // ---- reduce p1,p2 across the 16 tx lanes (within half-warps) ----
    #pragma unroll
    for (int r = 0; r < 4; r++) {
        float v1 = p1[r], v2 = p2[r];
        #pragma unroll
        for (int m = 8; m >= 1; m >>= 1) {
            v1 += __shfl_xor_sync(0xffffffffu, v1, m);
            v2 += __shfl_xor_sync(0xffffffffu, v2, m);
        }
        p1[r] = v1; p2[r] = v2;
    }
    if (tx == 0) {
        #pragma unroll
        for (int r = 0; r < 4; r++) {
            float S1 = fmaxf(p1[r], EPS_C);          // Ksum clamp
            float c  = rsqrtf(S1);                   // Ksum^(-alpha)
            float rs = fmaxf(c * p2[r], EPS_C);      // row_sum clamp
            sScale[4 * ty + r] = c / rs;
        }
    }
    __syncthreads();

    // ---- scaled writeback: y[row, h*64 + dh] ----
    #pragma unroll
    for (int r = 0; r < 4; r++) {
        float sc = sScale[4 * ty + r];
        float4 o = make_float4(acc[r][0] * sc, acc[r][1] * sc,
                               acc[r][2] * sc, acc[r][3] * sc);
        *reinterpret_cast<float4*>(
            &g_y[(size_t)(row0 + 4 * ty + r) * DOUT + h * DIM + 4 * tx]) = o;
    }
}

// ---------------------------------------------------------------------------
// Kernel 2: out = y @ W_O + b_O     (4096 x 512) @ (512 x 512)
// ---------------------------------------------------------------------------
#define BK2 64

__global__ void __launch_bounds__(256)
out_gemm_kernel(const float* __restrict__ WO, const float* __restrict__ bO,
                float* __restrict__ out)
{
    __shared__ float sYt[BK2 * LDA];   // y tile transposed [k][i]
    __shared__ float sB [BK2 * LDA];   // W_O tile [k][j]

    const int row0 = blockIdx.x * 64;
    const int col0 = blockIdx.y * 64;
    const int tid  = threadIdx.x;
    const int tx   = tid & 15;
    const int ty   = tid >> 4;

    float acc[4][4];
    #pragma unroll
    for (int r = 0; r < 4; r++)
        #pragma unroll
        for (int c = 0; c < 4; c++) acc[r][c] = 0.f;

    for (int k0 = 0; k0 < DOUT; k0 += BK2) {
        __syncthreads();
        for (int t = tid; t < 64 * BK2; t += 256) {
            int i = t >> 6, k = t & 63;
            sYt[k * LDA + i] = g_y[(size_t)(row0 + i) * DOUT + k0 + k];
        }
        for (int t = tid; t < BK2 * 64; t += 256) {
            int k = t >> 6, j = t & 63;
            sB[k * LDA + j] = WO[(size_t)(k0 + k) * DOUT + col0 + j];
        }
        __syncthreads();

        #pragma unroll 8
        for (int k = 0; k < BK2; k++) {
            float4 a = *reinterpret_cast<const float4*>(&sYt[k * LDA + 4 * ty]);
            float4 b = *reinterpret_cast<const float4*>(&sB [k * LDA + 4 * tx]);
            float av[4] = {a.x, a.y, a.z, a.w};
            float bv[4] = {b.x, b.y, b.z, b.w};
            #pragma unroll
            for (int r = 0; r < 4; r++)
                #pragma unroll
                for (int c = 0; c < 4; c++) acc[r][c] += av[r] * bv[c];
        }
    }

    #pragma unroll
    for (int r = 0; r < 4; r++) {
        int row = row0 + 4 * ty + r;
        #pragma unroll
        for (int c = 0; c < 4; c++) {
            int col = col0 + 4 * tx + c;
            out[(size_t)row * DOUT + col] = acc[r][c] + bO[col];
        }
    }
}

// ---------------------------------------------------------------------------
extern "C" void kernel_launch(void* const* d_in, const int* in_sizes, int n_in,
                              void* d_out, int out_size)
{
    const float* z  = (const float*)d_in[0];   // (4,1024,8,64)
    const float* R  = (const float*)d_in[1];   // (8,2048,64)
    const float* q  = (const float*)d_in[2];   // (8,2048)
    const float* W  = (const float*)d_in[3];   // (8,2048,64)
    const float* WO = (const float*)d_in[4];   // (512,512)
    const float* bO = (const float*)d_in[5];   // (512)
    float* out = (float*)d_out;                // (4,1024,512)
    (void)in_sizes; (void)n_in; (void)out_size;

    prep_kernel<<<(NHEAD * NLAND + 255) / 256, 256>>>(R, q);

    dim3 gridF(BS_ROWS / BM, NHEAD);           // (64, 8)
    fused_kernel<<<gridF, 256>>>(z, R, W);

    dim3 gridO(BS_ROWS / 64, DOUT / 64);       // (64, 8)
    out_gemm_kernel<<<gridO, 256>>>(WO, bO, out);
}

// round 4
// speedup vs baseline: 2.4830x; 2.4830x over previous
#include <cuda_runtime.h>
#include <cuda_bf16.h>
#include <cstdint>

// ---------------------------------------------------------------------------
// Problem constants
// ---------------------------------------------------------------------------
#define BS_ROWS 4096      // B*S
#define NHEAD   8
#define DIM     64        // d == D_head
#define NLAND   2048      // landmarks per head
#define DOUT    512
#define EPS_C   1e-12f

// ---------------------------------------------------------------------------
// Device-global scratch (no allocation allowed)
// ---------------------------------------------------------------------------
__device__ float g_R2[NHEAD * NLAND];
__device__ float g_qa[NHEAD * NLAND];
__device__ float g_y [BS_ROWS * DOUT];                  // 8 MB intermediate
__device__ __nv_bfloat16 g_RH[NHEAD * NLAND * DIM];     // R hi  [h][n][d]
__device__ __nv_bfloat16 g_RL[NHEAD * NLAND * DIM];     // R lo
__device__ __nv_bfloat16 g_WH[NHEAD * DIM * NLAND];     // W^T hi [h][dh][n]
__device__ __nv_bfloat16 g_WL[NHEAD * DIM * NLAND];     // W^T lo

// ---------------------------------------------------------------------------
// PTX helpers: cp.async, ldmatrix, mma (all sm_80-era, valid on sm_100 base)
// ---------------------------------------------------------------------------
__device__ __forceinline__ uint32_t smem_u32(const void* p) {
    return (uint32_t)__cvta_generic_to_shared(p);
}

__device__ __forceinline__ void cp16(uint32_t s, const void* g) {
    asm volatile("cp.async.cg.shared.global [%0], [%1], 16;" :: "r"(s), "l"(g));
}
#define CP_COMMIT() asm volatile("cp.async.commit_group;" ::: "memory")
#define CP_WAIT1()  asm volatile("cp.async.wait_group 1;" ::: "memory")
#define CP_WAIT0()  asm volatile("cp.async.wait_group 0;" ::: "memory")

__device__ __forceinline__ void ldm_x4(uint32_t* f, uint32_t addr) {
    asm volatile("ldmatrix.sync.aligned.m8n8.x4.shared.b16 {%0,%1,%2,%3}, [%4];"
        : "=r"(f[0]), "=r"(f[1]), "=r"(f[2]), "=r"(f[3]) : "r"(addr));
}

__device__ __forceinline__ void mma_bf16(float* c, const uint32_t* a,
                                         uint32_t b0, uint32_t b1) {
    asm volatile(
        "mma.sync.aligned.m16n8k16.row.col.f32.bf16.bf16.f32 "
        "{%0,%1,%2,%3}, {%4,%5,%6,%7}, {%8,%9}, {%0,%1,%2,%3};"
        : "+f"(c[0]), "+f"(c[1]), "+f"(c[2]), "+f"(c[3])
        : "r"(a[0]), "r"(a[1]), "r"(a[2]), "r"(a[3]), "r"(b0), "r"(b1));
}

// (f32,f32) -> packed bf16x2 hi + lo (residual)
__device__ __forceinline__ void split_pack(float e0, float e1,
                                           uint32_t& hi, uint32_t& lo)
{
    __nv_bfloat162 h2 = __float22bfloat162_rn(make_float2(e0, e1));
    float r0 = e0 - __bfloat162float(h2.x);
    float r1 = e1 - __bfloat162float(h2.y);
    __nv_bfloat162 l2 = __float22bfloat162_rn(make_float2(r0, r1));
    hi = *reinterpret_cast<uint32_t*>(&h2);
    lo = *reinterpret_cast<uint32_t*>(&l2);
}

// ---------------------------------------------------------------------------
// SMEM layout (bytes within one buffer). R tiles [128 n][64 k] halves with
// row stride 72 halves (144 B); W^T tiles [64 dh][128 n] stride 136 (272 B).
// Both strides give conflict-free ldmatrix (4r mod 32 distinct banks).
// ---------------------------------------------------------------------------
#define SR_B     144u
#define SW_B     272u
#define OFF_RH   0u
#define OFF_RL   18432u
#define OFF_WH   36864u
#define OFF_WL   54272u
#define OFF_R2   71680u
#define OFF_QA   72192u
#define BUF_B    72704u
#define SMEM_BYTES (2u * BUF_B)       // 145408

// ---------------------------------------------------------------------------
// Prep 1: per-landmark R2, qa, bf16 hi/lo split of R. warp per landmark.
// ---------------------------------------------------------------------------
__global__ void __launch_bounds__(256)
prep_land(const float* __restrict__ R, const float* __restrict__ q)
{
    int wid  = threadIdx.x >> 5, lane = threadIdx.x & 31;
    int idx  = blockIdx.x * 8 + wid;            // h*NLAND + n
    const float* r = R + (size_t)idx * DIM;
    float v0 = r[lane], v1 = r[lane + 32];
    __nv_bfloat16 h0 = __float2bfloat16_rn(v0);
    __nv_bfloat16 h1 = __float2bfloat16_rn(v1);
    g_RH[(size_t)idx * DIM + lane]      = h0;
    g_RH[(size_t)idx * DIM + lane + 32] = h1;
    g_RL[(size_t)idx * DIM + lane]      = __float2bfloat16_rn(v0 - __bfloat162float(h0));
    g_RL[(size_t)idx * DIM + lane + 32] = __float2bfloat16_rn(v1 - __bfloat162float(h1));
    float s = v0 * v0 + v1 * v1;
    #pragma unroll
    for (int m = 16; m >= 1; m >>= 1) s += __shfl_xor_sync(0xffffffffu, s, m);
    if (lane == 0) {
        g_R2[idx] = s;
        float qq = q[idx];
        qq = (qq > 0.f ? qq : 0.f) + EPS_C;
        g_qa[idx] = rsqrtf(qq);
    }
}

// ---------------------------------------------------------------------------
// Prep 2: W^T bf16 hi/lo [h][dh][n] via SMEM transpose
// ---------------------------------------------------------------------------
__global__ void __launch_bounds__(256)
prep_w(const float* __restrict__ W)
{
    __shared__ float sm[64][65];
    int h  = blockIdx.x >> 5;
    int n0 = (blockIdx.x & 31) * 64;
    for (int t = threadIdx.x; t < 4096; t += 256) {
        int i = t >> 6, d = t & 63;
        sm[i][d] = W[((size_t)(h * NLAND + n0 + i)) * DIM + d];
    }
    __syncthreads();
    for (int t = threadIdx.x; t < 4096; t += 256) {
        int d = t >> 6, i = t & 63;
        float v = sm[i][d];
        __nv_bfloat16 hh = __float2bfloat16_rn(v);
        size_t o = ((size_t)h * DIM + d) * NLAND + n0 + i;
        g_WH[o] = hh;
        g_WL[o] = __float2bfloat16_rn(v - __bfloat162float(hh));
    }
}

// ---------------------------------------------------------------------------
// Fused kernel: one CTA per (head, 128-row block), 256 threads (8 warps).
// Warp w owns rows [w*16, w*16+16) x all 128 landmark cols of each tile.
// ---------------------------------------------------------------------------
__device__ __forceinline__ void issue_tile_loads(char* smem, int buf, int h, int n0,
                                                 int tid)
{
    uint32_t sb = smem_u32(smem) + (uint32_t)buf * BUF_B;
    const __nv_bfloat16* rh = g_RH + ((size_t)h * NLAND + n0) * DIM;
    const __nv_bfloat16* rl = g_RL + ((size_t)h * NLAND + n0) * DIM;
    #pragma unroll
    for (int i = tid; i < 1024; i += 256) {
        int row = i >> 3, u = i & 7;
        cp16(sb + OFF_RH + row * SR_B + u * 16, rh + row * DIM + u * 8);
        cp16(sb + OFF_RL + row * SR_B + u * 16, rl + row * DIM + u * 8);
    }
    const __nv_bfloat16* wh = g_WH + (size_t)h * DIM * NLAND + n0;
    const __nv_bfloat16* wl = g_WL + (size_t)h * DIM * NLAND + n0;
    #pragma unroll
    for (int i = tid; i < 1024; i += 256) {
        int row = i >> 4, u = i & 15;
        cp16(sb + OFF_WH + row * SW_B + u * 16, wh + (size_t)row * NLAND + u * 8);
        cp16(sb + OFF_WL + row * SW_B + u * 16, wl + (size_t)row * NLAND + u * 8);
    }
    if (tid < 32) {
        cp16(sb + OFF_R2 + tid * 16, g_R2 + h * NLAND + n0 + tid * 4);
        cp16(sb + OFF_QA + tid * 16, g_qa + h * NLAND + n0 + tid * 4);
    }
}

__global__ void __launch_bounds__(256, 1)
fused_mma(const float* __restrict__ z)
{
    extern __shared__ __align__(16) char smem[];
    const int tid  = threadIdx.x;
    const int warp = tid >> 5;
    const int lane = tid & 31;
    const int h    = blockIdx.y;
    const int row0 = blockIdx.x * 128;
    const int g    = lane >> 2;          // 0..7
    const int t4   = lane & 3;           // 0..3
    const int wrow = warp * 16;
    const uint32_t sbase = smem_u32(smem);

    // ldmatrix per-lane offsets (n_add rows, k_add halves)
    const int n_add = ((lane >> 4) & 1) * 8 + (lane & 7);
    const int k_add = ((lane >> 3) & 1) * 8;
    const uint32_t laneR = (uint32_t)(n_add * SR_B + k_add * 2);
    const uint32_t laneW = (uint32_t)(n_add * SW_B + k_add * 2);

    // ---- prologue: kick cp.async for tile 0 into buf 0 ----
    issue_tile_loads(smem, 0, h, 0, tid);
    CP_COMMIT();

    // ---- stage z block (fp32) into buf1 region, build Z A-frags ----
    float* zstage = (float*)(smem + BUF_B);     // [128][68] floats (34816 B < BUF_B)
    {
        const float4* zsrc = reinterpret_cast<const float4*>(z);
        #pragma unroll
        for (int i = tid; i < 2048; i += 256) {
            int r = i >> 4, c4 = i & 15;
            float4 v = zsrc[(((size_t)(row0 + r) * NHEAD + h) * DIM >> 2) + c4];
            *reinterpret_cast<float4*>(zstage + r * 68 + c4 * 4) = v;
        }
    }
    __syncthreads();

    const int r0 = wrow + g, r1 = r0 + 8;       // this thread's 2 rows (local)
    float z2a = 0.f, z2b = 0.f;
    #pragma unroll
    for (int k = 0; k < DIM; k++) {
        float va = zstage[r0 * 68 + k];
        float vb = zstage[r1 * 68 + k];
        z2a += va * va; z2b += vb * vb;
    }

    uint32_t zh[4][4], zl[4][4];
    #pragma unroll
    for (int kc = 0; kc < 4; kc++) {
        int k0 = kc * 16 + 2 * t4;
        split_pack(zstage[r0 * 68 + k0],     zstage[r0 * 68 + k0 + 1], zh[kc][0], zl[kc][0]);
        split_pack(zstage[r1 * 68 + k0],     zstage[r1 * 68 + k0 + 1], zh[kc][1], zl[kc][1]);
        split_pack(zstage[r0 * 68 + k0 + 8], zstage[r0 * 68 + k0 + 9], zh[kc][2], zl[kc][2]);
        split_pack(zstage[r1 * 68 + k0 + 8], zstage[r1 * 68 + k0 + 9], zh[kc][3], zl[kc][3]);
    }
    __syncthreads();   // done with buf1 region before tile-1 cp.async hits it

    float y[8][4];
    #pragma unroll
    for (int nt = 0; nt < 8; nt++)
        #pragma unroll
        for (int e = 0; e < 4; e++) y[nt][e] = 0.f;

    float p1a = 0.f, p1b = 0.f, p2a = 0.f, p2b = 0.f;

    for (int t = 0; t < 16; t++) {
        const int cur = t & 1;
        if (t < 15) {
            issue_tile_loads(smem, cur ^ 1, h, (t + 1) * 128, tid);
            CP_COMMIT();
            CP_WAIT1();
        } else {
            CP_WAIT0();
        }
        __syncthreads();

        const uint32_t sb = sbase + (uint32_t)cur * BUF_B;
        const uint32_t rbH = sb + OFF_RH + laneR;
        const uint32_t rbL = sb + OFF_RL + laneR;
        const float* r2p = (const float*)(smem + cur * BUF_B + OFF_R2);
        const float* qap = (const float*)(smem + cur * BUF_B + OFF_QA);

        // ---- GEMM1: c[128 rows x 128 land] (warp: 16 x 128) ----
        float c[16][4];
        #pragma unroll
        for (int nt = 0; nt < 16; nt++)
            #pragma unroll
            for (int e = 0; e < 4; e++) c[nt][e] = 0.f;

        #pragma unroll
        for (int kc = 0; kc < 4; kc++) {
            #pragma unroll
            for (int ntp = 0; ntp < 8; ntp++) {
                uint32_t off = (uint32_t)(ntp * 16) * SR_B + (uint32_t)kc * 32;
                uint32_t rh[4], rl[4];
                ldm_x4(rh, rbH + off);
                ldm_x4(rl, rbL + off);
                mma_bf16(c[2 * ntp],     zh[kc], rh[0], rh[1]);
                mma_bf16(c[2 * ntp],     zh[kc], rl[0], rl[1]);
                mma_bf16(c[2 * ntp],     zl[kc], rh[0], rh[1]);
                mma_bf16(c[2 * ntp + 1], zh[kc], rh[2], rh[3]);
                mma_bf16(c[2 * ntp + 1], zh[kc], rl[2], rl[3]);
                mma_bf16(c[2 * ntp + 1], zl[kc], rh[2], rh[3]);
            }
        }

        // ---- epilogue + GEMM2, interleaved per landmark k-chunk of 16 ----
        const uint32_t wbH = sb + OFF_WH + laneW;
        const uint32_t wbL = sb + OFF_WL + laneW;
        #pragma unroll
        for (int kch = 0; kch < 8; kch++) {
            const int ct0 = 2 * kch, ct1 = 2 * kch + 1;
            const int col0 = ct0 * 8 + 2 * t4;       // cols col0,col0+1
            const int col1 = ct1 * 8 + 2 * t4;       // cols col1,col1+1
            float r2_0 = r2p[col0], r2_1 = r2p[col0 + 1];
            float r2_2 = r2p[col1], r2_3 = r2p[col1 + 1];
            float qa_0 = qap[col0], qa_1 = qap[col0 + 1];
            float qa_2 = qap[col1], qa_3 = qap[col1 + 1];

            float K00 = __expf(-0.5f * fmaxf(fmaf(-2.f, c[ct0][0], z2a) + r2_0, 0.f));
            float K01 = __expf(-0.5f * fmaxf(fmaf(-2.f, c[ct0][1], z2a) + r2_1, 0.f));
            float K02 = __expf(-0.5f * fmaxf(fmaf(-2.f, c[ct0][2], z2b) + r2_0, 0.f));
            float K03 = __expf(-0.5f * fmaxf(fmaf(-2.f, c[ct0][3], z2b) + r2_1, 0.f));
            float K10 = __expf(-0.5f * fmaxf(fmaf(-2.f, c[ct1][0], z2a) + r2_2, 0.f));
            float K11 = __expf(-0.5f * fmaxf(fmaf(-2.f, c[ct1][1], z2a) + r2_3, 0.f));
            float K12 = __expf(-0.5f * fmaxf(fmaf(-2.f, c[ct1][2], z2b) + r2_2, 0.f));
            float K13 = __expf(-0.5f * fmaxf(fmaf(-2.f, c[ct1][3], z2b) + r2_3, 0.f));

            p1a += K00 + K01 + K10 + K11;
            p1b += K02 + K03 + K12 + K13;

            float kt00 = K00 * qa_0, kt01 = K01 * qa_1;
            float kt02 = K02 * qa_0, kt03 = K03 * qa_1;
            float kt10 = K10 * qa_2, kt11 = K11 * qa_3;
            float kt12 = K12 * qa_2, kt13 = K13 * qa_3;

            p2a += kt00 + kt01 + kt10 + kt11;
            p2b += kt02 + kt03 + kt12 + kt13;

            uint32_t ah[4], al[4];
            split_pack(kt00, kt01, ah[0], al[0]);   // row g,   k lo pair
            split_pack(kt02, kt03, ah[1], al[1]);   // row g+8, k lo
            split_pack(kt10, kt11, ah[2], al[2]);   // row g,   k hi
            split_pack(kt12, kt13, ah[3], al[3]);   // row g+8, k hi

            #pragma unroll
            for (int ntp = 0; ntp < 4; ntp++) {
                uint32_t off = (uint32_t)(ntp * 16) * SW_B + (uint32_t)kch * 32;
                uint32_t wh[4], wl[4];
                ldm_x4(wh, wbH + off);
                ldm_x4(wl, wbL + off);
                mma_bf16(y[2 * ntp],     ah, wh[0], wh[1]);
                mma_bf16(y[2 * ntp],     ah, wl[0], wl[1]);
                mma_bf16(y[2 * ntp],     al, wh[0], wh[1]);
                mma_bf16(y[2 * ntp + 1], ah, wh[2], wh[3]);
                mma_bf16(y[2 * ntp + 1], ah, wl[2], wl[3]);
                mma_bf16(y[2 * ntp + 1], al, wh[2], wh[3]);
            }
        }
        __syncthreads();   // tile buffer free for reuse
    }

    // ---- reduce row sums across the 4 lanes sharing each row ----
    #pragma unroll
    for (int m = 1; m <= 2; m <<= 1) {
        p1a += __shfl_xor_sync(0xffffffffu, p1a, m);
        p1b += __shfl_xor_sync(0xffffffffu, p1b, m);
        p2a += __shfl_xor_sync(0xffffffffu, p2a, m);
        p2b += __shfl_xor_sync(0xffffffffu, p2b, m);
    }
    float cc0 = rsqrtf(fmaxf(p1a, EPS_C));
    float cc1 = rsqrtf(fmaxf(p1b, EPS_C));
    float sc0 = cc0 / fmaxf(cc0 * p2a, EPS_C);
    float sc1 = cc1 / fmaxf(cc1 * p2b, EPS_C);

    // ---- write y block: rows row0+r0 / row0+r1, cols h*64 + nt*8 + 2t ----
    float* dst0 = g_y + (size_t)(row0 + r0) * DOUT + h * DIM + 2 * t4;
    float* dst1 = g_y + (size_t)(row0 + r1) * DOUT + h * DIM + 2 * t4;
    #pragma unroll
    for (int nt = 0; nt < 8; nt++) {
        *reinterpret_cast<float2*>(dst0 + nt * 8) =
            make_float2(y[nt][0] * sc0, y[nt][1] * sc0);
        *reinterpret_cast<float2*>(dst1 + nt * 8) =
            make_float2(y[nt][2] * sc1, y[nt][3] * sc1);
    }
}

// ---------------------------------------------------------------------------
// Kernel: out = y @ W_O + b_O     (4096 x 512) @ (512 x 512)   [SIMT fp32]
// ---------------------------------------------------------------------------
#define OG_LDA 68

__global__ void __launch_bounds__(256)
out_gemm_kernel(const float* __restrict__ WO, const float* __restrict__ bO,
                float* __restrict__ out)
{
    __shared__ float sYt[64 * OG_LDA];
    __shared__ float sB [64 * OG_LDA];

    const int row0 = blockIdx.x * 64;
    const int col0 = blockIdx.y * 64;
    const int tid  = threadIdx.x;
    const int tx   = tid & 15;
    const int ty   = tid >> 4;

    float acc[4][4];
    #pragma unroll
    for (int r = 0; r < 4; r++)
        #pragma unroll
        for (int c = 0; c < 4; c++) acc[r][c] = 0.f;

    for (int k0 = 0; k0 < DOUT; k0 += 64) {
        __syncthreads();
        for (int t = tid; t < 64 * 64; t += 256) {
            int i = t >> 6, k = t & 63;
            sYt[k * OG_LDA + i] = g_y[(size_t)(row0 + i) * DOUT + k0 + k];
        }
        for (int t = tid; t < 64 * 64; t += 256) {
            int k = t >> 6, j = t & 63;
            sB[k * OG_LDA + j] = WO[(size_t)(k0 + k) * DOUT + col0 + j];
        }
        __syncthreads();

        #pragma unroll 8
        for (int k = 0; k < 64; k++) {
            float4 a = *reinterpret_cast<const float4*>(&sYt[k * OG_LDA + 4 * ty]);
            float4 b = *reinterpret_cast<const float4*>(&sB [k * OG_LDA + 4 * tx]);
            float av[4] = {a.x, a.y, a.z, a.w};
            float bv[4] = {b.x, b.y, b.z, b.w};
            #pragma unroll
            for (int r = 0; r < 4; r++)
                #pragma unroll
                for (int c = 0; c < 4; c++) acc[r][c] += av[r] * bv[c];
        }
    }

    #pragma unroll
    for (int r = 0; r < 4; r++) {
        int row = row0 + 4 * ty + r;
        #pragma unroll
        for (int c = 0; c < 4; c++) {
            int col = col0 + 4 * tx + c;
            out[(size_t)row * DOUT + col] = acc[r][c] + bO[col];
        }
    }
}

// ---------------------------------------------------------------------------
extern "C" void kernel_launch(void* const* d_in, const int* in_sizes, int n_in,
                              void* d_out, int out_size)
{
    const float* z  = (const float*)d_in[0];   // (4,1024,8,64)
    const float* R  = (const float*)d_in[1];   // (8,2048,64)
    const float* q  = (const float*)d_in[2];   // (8,2048)
    const float* W  = (const float*)d_in[3];   // (8,2048,64)
    const float* WO = (const float*)d_in[4];   // (512,512)
    const float* bO = (const float*)d_in[5];   // (512)
    float* out = (float*)d_out;                // (4,1024,512)
    (void)in_sizes; (void)n_in; (void)out_size;

    cudaFuncSetAttribute(fused_mma, cudaFuncAttributeMaxDynamicSharedMemorySize,
                         SMEM_BYTES);

    prep_land<<<NHEAD * NLAND / 8, 256>>>(R, q);
    prep_w<<<NHEAD * (NLAND / 64), 256>>>(W);

    dim3 gridF(BS_ROWS / 128, NHEAD);          // (32, 8)
    fused_mma<<<gridF, 256, SMEM_BYTES>>>(z);

    dim3 gridO(BS_ROWS / 64, DOUT / 64);       // (64, 8)
    out_gemm_kernel<<<gridO, 256>>>(WO, bO, out);
}

// round 5
// speedup vs baseline: 3.1165x; 1.2551x over previous
#include <cuda_runtime.h>
#include <cuda_bf16.h>
#include <cstdint>

// ---------------------------------------------------------------------------
// Problem constants
// ---------------------------------------------------------------------------
#define BS_ROWS 4096      // B*S
#define NHEAD   8
#define DIM     64        // d == D_head
#define NLAND   2048      // landmarks per head
#define DOUT    512
#define EPS_C   1e-12f

// ---------------------------------------------------------------------------
// Device-global scratch (no allocation allowed)
// ---------------------------------------------------------------------------
__device__ float g_R2[NHEAD * NLAND];
__device__ float g_qa[NHEAD * NLAND];
__device__ __nv_bfloat16 g_RH[NHEAD * NLAND * DIM];     // R hi  [h][n][d]
__device__ __nv_bfloat16 g_RL[NHEAD * NLAND * DIM];     // R lo
__device__ __nv_bfloat16 g_WH[NHEAD * DIM * NLAND];     // W^T hi [h][dh][n]
__device__ __nv_bfloat16 g_WL[NHEAD * DIM * NLAND];     // W^T lo
__device__ __nv_bfloat16 g_YH[BS_ROWS * DOUT];          // y hi [row][col]
__device__ __nv_bfloat16 g_YL[BS_ROWS * DOUT];          // y lo
__device__ __nv_bfloat16 g_WOH[DOUT * DOUT];            // W_O^T hi [col][k]
__device__ __nv_bfloat16 g_WOL[DOUT * DOUT];            // W_O^T lo

// ---------------------------------------------------------------------------
// PTX helpers: cp.async, ldmatrix, mma (all sm_80-era, valid on sm_100 base)
// ---------------------------------------------------------------------------
__device__ __forceinline__ uint32_t smem_u32(const void* p) {
    return (uint32_t)__cvta_generic_to_shared(p);
}

__device__ __forceinline__ void cp16(uint32_t s, const void* g) {
    asm volatile("cp.async.cg.shared.global [%0], [%1], 16;" :: "r"(s), "l"(g));
}
#define CP_COMMIT() asm volatile("cp.async.commit_group;" ::: "memory")
#define CP_WAIT1()  asm volatile("cp.async.wait_group 1;" ::: "memory")
#define CP_WAIT0()  asm volatile("cp.async.wait_group 0;" ::: "memory")

__device__ __forceinline__ void ldm_x4(uint32_t* f, uint32_t addr) {
    asm volatile("ldmatrix.sync.aligned.m8n8.x4.shared.b16 {%0,%1,%2,%3}, [%4];"
        : "=r"(f[0]), "=r"(f[1]), "=r"(f[2]), "=r"(f[3]) : "r"(addr));
}

__device__ __forceinline__ void mma_bf16(float* c, const uint32_t* a,
                                         uint32_t b0, uint32_t b1) {
    asm volatile(
        "mma.sync.aligned.m16n8k16.row.col.f32.bf16.bf16.f32 "
        "{%0,%1,%2,%3}, {%4,%5,%6,%7}, {%8,%9}, {%0,%1,%2,%3};"
        : "+f"(c[0]), "+f"(c[1]), "+f"(c[2]), "+f"(c[3])
        : "r"(a[0]), "r"(a[1]), "r"(a[2]), "r"(a[3]), "r"(b0), "r"(b1));
}

// (f32,f32) -> packed bf16x2 hi + lo (residual)
__device__ __forceinline__ void split_pack(float e0, float e1,
                                           uint32_t& hi, uint32_t& lo)
{
    __nv_bfloat162 h2 = __float22bfloat162_rn(make_float2(e0, e1));
    float r0 = e0 - __bfloat162float(h2.x);
    float r1 = e1 - __bfloat162float(h2.y);
    __nv_bfloat162 l2 = __float22bfloat162_rn(make_float2(r0, r1));
    hi = *reinterpret_cast<uint32_t*>(&h2);
    lo = *reinterpret_cast<uint32_t*>(&l2);
}

// ---------------------------------------------------------------------------
// Fused-kernel SMEM layout (bytes within one buffer).
// ---------------------------------------------------------------------------
#define SR_B     144u
#define SW_B     272u
#define OFF_RH   0u
#define OFF_RL   18432u
#define OFF_WH   36864u
#define OFF_WL   54272u
#define OFF_R2   71680u
#define OFF_QA   72192u
#define BUF_B    72704u
#define SMEM_BYTES (2u * BUF_B)       // 145408

// ---------------------------------------------------------------------------
// Prep 1: per-landmark R2, qa, bf16 hi/lo split of R. warp per landmark.
// ---------------------------------------------------------------------------
__global__ void __launch_bounds__(256)
prep_land(const float* __restrict__ R, const float* __restrict__ q)
{
    int wid  = threadIdx.x >> 5, lane = threadIdx.x & 31;
    int idx  = blockIdx.x * 8 + wid;            // h*NLAND + n
    const float* r = R + (size_t)idx * DIM;
    float v0 = r[lane], v1 = r[lane + 32];
    __nv_bfloat16 h0 = __float2bfloat16_rn(v0);
    __nv_bfloat16 h1 = __float2bfloat16_rn(v1);
    g_RH[(size_t)idx * DIM + lane]      = h0;
    g_RH[(size_t)idx * DIM + lane + 32] = h1;
    g_RL[(size_t)idx * DIM + lane]      = __float2bfloat16_rn(v0 - __bfloat162float(h0));
    g_RL[(size_t)idx * DIM + lane + 32] = __float2bfloat16_rn(v1 - __bfloat162float(h1));
    float s = v0 * v0 + v1 * v1;
    #pragma unroll
    for (int m = 16; m >= 1; m >>= 1) s += __shfl_xor_sync(0xffffffffu, s, m);
    if (lane == 0) {
        g_R2[idx] = s;
        float qq = q[idx];
        qq = (qq > 0.f ? qq : 0.f) + EPS_C;
        g_qa[idx] = rsqrtf(qq);
    }
}

// ---------------------------------------------------------------------------
// Prep 2: W^T bf16 hi/lo [h][dh][n] via SMEM transpose
// ---------------------------------------------------------------------------
__global__ void __launch_bounds__(256)
prep_w(const float* __restrict__ W)
{
    __shared__ float sm[64][65];
    int h  = blockIdx.x >> 5;
    int n0 = (blockIdx.x & 31) * 64;
    for (int t = threadIdx.x; t < 4096; t += 256) {
        int i = t >> 6, d = t & 63;
        sm[i][d] = W[((size_t)(h * NLAND + n0 + i)) * DIM + d];
    }
    __syncthreads();
    for (int t = threadIdx.x; t < 4096; t += 256) {
        int d = t >> 6, i = t & 63;
        float v = sm[i][d];
        __nv_bfloat16 hh = __float2bfloat16_rn(v);
        size_t o = ((size_t)h * DIM + d) * NLAND + n0 + i;
        g_WH[o] = hh;
        g_WL[o] = __float2bfloat16_rn(v - __bfloat162float(hh));
    }
}

// ---------------------------------------------------------------------------
// Prep 3: W_O^T bf16 hi/lo [col][k] via SMEM transpose (512x512)
// ---------------------------------------------------------------------------
__global__ void __launch_bounds__(256)
prep_wo(const float* __restrict__ WO)
{
    __shared__ float sm[64][65];
    int kb = blockIdx.x >> 3;                   // k block
    int cb = blockIdx.x & 7;                    // col block
    int k0 = kb * 64, c0 = cb * 64;
    for (int t = threadIdx.x; t < 4096; t += 256) {
        int i = t >> 6, d = t & 63;
        sm[i][d] = WO[(size_t)(k0 + i) * DOUT + c0 + d];
    }
    __syncthreads();
    for (int t = threadIdx.x; t < 4096; t += 256) {
        int d = t >> 6, i = t & 63;
        float v = sm[i][d];
        __nv_bfloat16 hh = __float2bfloat16_rn(v);
        size_t o = (size_t)(c0 + d) * DOUT + k0 + i;
        g_WOH[o] = hh;
        g_WOL[o] = __float2bfloat16_rn(v - __bfloat162float(hh));
    }
}

// ---------------------------------------------------------------------------
// Fused kernel: one CTA per (head, 128-row block), 256 threads (8 warps).
// ---------------------------------------------------------------------------
__device__ __forceinline__ void issue_tile_loads(char* smem, int buf, int h, int n0,
                                                 int tid)
{
    uint32_t sb = smem_u32(smem) + (uint32_t)buf * BUF_B;
    const __nv_bfloat16* rh = g_RH + ((size_t)h * NLAND + n0) * DIM;
    const __nv_bfloat16* rl = g_RL + ((size_t)h * NLAND + n0) * DIM;
    #pragma unroll
    for (int i = tid; i < 1024; i += 256) {
        int row = i >> 3, u = i & 7;
        cp16(sb + OFF_RH + row * SR_B + u * 16, rh + row * DIM + u * 8);
        cp16(sb + OFF_RL + row * SR_B + u * 16, rl + row * DIM + u * 8);
    }
    const __nv_bfloat16* wh = g_WH + (size_t)h * DIM * NLAND + n0;
    const __nv_bfloat16* wl = g_WL + (size_t)h * DIM * NLAND + n0;
    #pragma unroll
    for (int i = tid; i < 1024; i += 256) {
        int row = i >> 4, u = i & 15;
        cp16(sb + OFF_WH + row * SW_B + u * 16, wh + (size_t)row * NLAND + u * 8);
        cp16(sb + OFF_WL + row * SW_B + u * 16, wl + (size_t)row * NLAND + u * 8);
    }
    if (tid < 32) {
        cp16(sb + OFF_R2 + tid * 16, g_R2 + h * NLAND + n0 + tid * 4);
        cp16(sb + OFF_QA + tid * 16, g_qa + h * NLAND + n0 + tid * 4);
    }
}

__global__ void __launch_bounds__(256, 1)
fused_mma(const float* __restrict__ z)
{
    extern __shared__ __align__(16) char smem[];
    const int tid  = threadIdx.x;
    const int warp = tid >> 5;
    const int lane = tid & 31;
    const int h    = blockIdx.y;
    const int row0 = blockIdx.x * 128;
    const int g    = lane >> 2;          // 0..7
    const int t4   = lane & 3;           // 0..3
    const int wrow = warp * 16;
    const uint32_t sbase = smem_u32(smem);

    const int n_add = ((lane >> 4) & 1) * 8 + (lane & 7);
    const int k_add = ((lane >> 3) & 1) * 8;
    const uint32_t laneR = (uint32_t)(n_add * SR_B + k_add * 2);
    const uint32_t laneW = (uint32_t)(n_add * SW_B + k_add * 2);

    // ---- prologue: kick cp.async for tile 0 into buf 0 ----
    issue_tile_loads(smem, 0, h, 0, tid);
    CP_COMMIT();

    // ---- stage z block (fp32) into buf1 region, build Z A-frags ----
    float* zstage = (float*)(smem + BUF_B);
    {
        const float4* zsrc = reinterpret_cast<const float4*>(z);
        #pragma unroll
        for (int i = tid; i < 2048; i += 256) {
            int r = i >> 4, c4 = i & 15;
            float4 v = zsrc[(((size_t)(row0 + r) * NHEAD + h) * DIM >> 2) + c4];
            *reinterpret_cast<float4*>(zstage + r * 68 + c4 * 4) = v;
        }
    }
    __syncthreads();

    const int r0 = wrow + g, r1 = r0 + 8;
    float z2a = 0.f, z2b = 0.f;
    #pragma unroll
    for (int k = 0; k < DIM; k++) {
        float va = zstage[r0 * 68 + k];
        float vb = zstage[r1 * 68 + k];
        z2a += va * va; z2b += vb * vb;
    }

    uint32_t zh[4][4], zl[4][4];
    #pragma unroll
    for (int kc = 0; kc < 4; kc++) {
        int k0 = kc * 16 + 2 * t4;
        split_pack(zstage[r0 * 68 + k0],     zstage[r0 * 68 + k0 + 1], zh[kc][0], zl[kc][0]);
        split_pack(zstage[r1 * 68 + k0],     zstage[r1 * 68 + k0 + 1], zh[kc][1], zl[kc][1]);
        split_pack(zstage[r0 * 68 + k0 + 8], zstage[r0 * 68 + k0 + 9], zh[kc][2], zl[kc][2]);
        split_pack(zstage[r1 * 68 + k0 + 8], zstage[r1 * 68 + k0 + 9], zh[kc][3], zl[kc][3]);
    }
    __syncthreads();

    float y[8][4];
    #pragma unroll
    for (int nt = 0; nt < 8; nt++)
        #pragma unroll
        for (int e = 0; e < 4; e++) y[nt][e] = 0.f;

    float p1a = 0.f, p1b = 0.f, p2a = 0.f, p2b = 0.f;

    for (int t = 0; t < 16; t++) {
        const int cur = t & 1;
        if (t < 15) {
            issue_tile_loads(smem, cur ^ 1, h, (t + 1) * 128, tid);
            CP_COMMIT();
            CP_WAIT1();
        } else {
            CP_WAIT0();
        }
        __syncthreads();

        const uint32_t sb = sbase + (uint32_t)cur * BUF_B;
        const uint32_t rbH = sb + OFF_RH + laneR;
        const uint32_t rbL = sb + OFF_RL + laneR;
        const float* r2p = (const float*)(smem + cur * BUF_B + OFF_R2);
        const float* qap = (const float*)(smem + cur * BUF_B + OFF_QA);

        // ---- GEMM1 ----
        float c[16][4];
        #pragma unroll
        for (int nt = 0; nt < 16; nt++)
            #pragma unroll
            for (int e = 0; e < 4; e++) c[nt][e] = 0.f;

        #pragma unroll
        for (int kc = 0; kc < 4; kc++) {
            #pragma unroll
            for (int ntp = 0; ntp < 8; ntp++) {
                uint32_t off = (uint32_t)(ntp * 16) * SR_B + (uint32_t)kc * 32;
                uint32_t rh[4], rl[4];
                ldm_x4(rh, rbH + off);
                ldm_x4(rl, rbL + off);
                mma_bf16(c[2 * ntp],     zh[kc], rh[0], rh[1]);
                mma_bf16(c[2 * ntp],     zh[kc], rl[0], rl[1]);
                mma_bf16(c[2 * ntp],     zl[kc], rh[0], rh[1]);
                mma_bf16(c[2 * ntp + 1], zh[kc], rh[2], rh[3]);
                mma_bf16(c[2 * ntp + 1], zh[kc], rl[2], rl[3]);
                mma_bf16(c[2 * ntp + 1], zl[kc], rh[2], rh[3]);
            }
        }

        // ---- epilogue + GEMM2 interleaved ----
        const uint32_t wbH = sb + OFF_WH + laneW;
        const uint32_t wbL = sb + OFF_WL + laneW;
        #pragma unroll
        for (int kch = 0; kch < 8; kch++) {
            const int ct0 = 2 * kch, ct1 = 2 * kch + 1;
            const int col0 = ct0 * 8 + 2 * t4;
            const int col1 = ct1 * 8 + 2 * t4;
            float r2_0 = r2p[col0], r2_1 = r2p[col0 + 1];
            float r2_2 = r2p[col1], r2_3 = r2p[col1 + 1];
            float qa_0 = qap[col0], qa_1 = qap[col0 + 1];
            float qa_2 = qap[col1], qa_3 = qap[col1 + 1];

            float K00 = __expf(-0.5f * fmaxf(fmaf(-2.f, c[ct0][0], z2a) + r2_0, 0.f));
            float K01 = __expf(-0.5f * fmaxf(fmaf(-2.f, c[ct0][1], z2a) + r2_1, 0.f));
            float K02 = __expf(-0.5f * fmaxf(fmaf(-2.f, c[ct0][2], z2b) + r2_0, 0.f));
            float K03 = __expf(-0.5f * fmaxf(fmaf(-2.f, c[ct0][3], z2b) + r2_1, 0.f));
            float K10 = __expf(-0.5f * fmaxf(fmaf(-2.f, c[ct1][0], z2a) + r2_2, 0.f));
            float K11 = __expf(-0.5f * fmaxf(fmaf(-2.f, c[ct1][1], z2a) + r2_3, 0.f));
            float K12 = __expf(-0.5f * fmaxf(fmaf(-2.f, c[ct1][2], z2b) + r2_2, 0.f));
            float K13 = __expf(-0.5f * fmaxf(fmaf(-2.f, c[ct1][3], z2b) + r2_3, 0.f));

            p1a += K00 + K01 + K10 + K11;
            p1b += K02 + K03 + K12 + K13;

            float kt00 = K00 * qa_0, kt01 = K01 * qa_1;
            float kt02 = K02 * qa_0, kt03 = K03 * qa_1;
            float kt10 = K10 * qa_2, kt11 = K11 * qa_3;
            float kt12 = K12 * qa_2, kt13 = K13 * qa_3;

            p2a += kt00 + kt01 + kt10 + kt11;
            p2b += kt02 + kt03 + kt12 + kt13;

            uint32_t ah[4], al[4];
            split_pack(kt00, kt01, ah[0], al[0]);
            split_pack(kt02, kt03, ah[1], al[1]);
            split_pack(kt10, kt11, ah[2], al[2]);
            split_pack(kt12, kt13, ah[3], al[3]);

            #pragma unroll
            for (int ntp = 0; ntp < 4; ntp++) {
                uint32_t off = (uint32_t)(ntp * 16) * SW_B + (uint32_t)kch * 32;
                uint32_t wh[4], wl[4];
                ldm_x4(wh, wbH + off);
                ldm_x4(wl, wbL + off);
                mma_bf16(y[2 * ntp],     ah, wh[0], wh[1]);
                mma_bf16(y[2 * ntp],     ah, wl[0], wl[1]);
                mma_bf16(y[2 * ntp],     al, wh[0], wh[1]);
                mma_bf16(y[2 * ntp + 1], ah, wh[2], wh[3]);
                mma_bf16(y[2 * ntp + 1], ah, wl[2], wl[3]);
                mma_bf16(y[2 * ntp + 1], al, wh[2], wh[3]);
            }
        }
        __syncthreads();
    }

    // ---- row-sum reduction + scale ----
    #pragma unroll
    for (int m = 1; m <= 2; m <<= 1) {
        p1a += __shfl_xor_sync(0xffffffffu, p1a, m);
        p1b += __shfl_xor_sync(0xffffffffu, p1b, m);
        p2a += __shfl_xor_sync(0xffffffffu, p2a, m);
        p2b += __shfl_xor_sync(0xffffffffu, p2b, m);
    }
    float cc0 = rsqrtf(fmaxf(p1a, EPS_C));
    float cc1 = rsqrtf(fmaxf(p1b, EPS_C));
    float sc0 = cc0 / fmaxf(cc0 * p2a, EPS_C);
    float sc1 = cc1 / fmaxf(cc1 * p2b, EPS_C);

    // ---- write y as bf16 hi/lo (ldmatrix-ready for out_tc) ----
    size_t o0 = (size_t)(row0 + r0) * DOUT + h * DIM + 2 * t4;
    size_t o1 = (size_t)(row0 + r1) * DOUT + h * DIM + 2 * t4;
    #pragma unroll
    for (int nt = 0; nt < 8; nt++) {
        uint32_t hi, lo;
        split_pack(y[nt][0] * sc0, y[nt][1] * sc0, hi, lo);
        *reinterpret_cast<uint32_t*>(g_YH + o0 + nt * 8) = hi;
        *reinterpret_cast<uint32_t*>(g_YL + o0 + nt * 8) = lo;
        split_pack(y[nt][2] * sc1, y[nt][3] * sc1, hi, lo);
        *reinterpret_cast<uint32_t*>(g_YH + o1 + nt * 8) = hi;
        *reinterpret_cast<uint32_t*>(g_YL + o1 + nt * 8) = lo;
    }
}

// ---------------------------------------------------------------------------
// out = y @ W_O + b_O  via bf16 mma hi/lo. Tile 128x128, K=512 in 64-blocks.
// SMEM per buffer: A hi/lo + B hi/lo, each [128][64] halves, stride 144 B.
// ---------------------------------------------------------------------------
#define OB_STRIDE 144u
#define OB_MAT    18432u                 // 128 * 144
#define OB_AH     0u
#define OB_AL     18432u
#define OB_BH     36864u
#define OB_BL     55296u
#define OB_BUF    73728u
#define OUT_SMEM  (2u * OB_BUF)          // 147456

__device__ __forceinline__ void issue_out_loads(char* smem, int buf, int row0,
                                                int col0, int k0, int tid)
{
    uint32_t sb = smem_u32(smem) + (uint32_t)buf * OB_BUF;
    #pragma unroll
    for (int i = tid; i < 1024; i += 256) {
        int row = i >> 3, u = i & 7;
        size_t ga = (size_t)(row0 + row) * DOUT + k0 + u * 8;
        cp16(sb + OB_AH + row * OB_STRIDE + u * 16, g_YH + ga);
        cp16(sb + OB_AL + row * OB_STRIDE + u * 16, g_YL + ga);
        size_t gb = (size_t)(col0 + row) * DOUT + k0 + u * 8;
        cp16(sb + OB_BH + row * OB_STRIDE + u * 16, g_WOH + gb);
        cp16(sb + OB_BL + row * OB_STRIDE + u * 16, g_WOL + gb);
    }
}

__global__ void __launch_bounds__(256, 1)
out_tc(const float* __restrict__ bO, float* __restrict__ out)
{
    extern __shared__ __align__(16) char smem[];
    const int tid  = threadIdx.x;
    const int warp = tid >> 5;
    const int lane = tid & 31;
    const int row0 = blockIdx.x * 128;
    const int col0 = blockIdx.y * 128;
    const int g    = lane >> 2;
    const int t4   = lane & 3;
    const int wrow = warp * 16;
    const uint32_t sbase = smem_u32(smem);

    const int n_add = ((lane >> 4) & 1) * 8 + (lane & 7);
    const int k_add = ((lane >> 3) & 1) * 8;
    const uint32_t laneO = (uint32_t)(n_add * OB_STRIDE + k_add * 2);

    issue_out_loads(smem, 0, row0, col0, 0, tid);
    CP_COMMIT();

    float y[16][4];
    #pragma unroll
    for (int nt = 0; nt < 16; nt++)
        #pragma unroll
        for (int e = 0; e < 4; e++) y[nt][e] = 0.f;

    for (int kb = 0; kb < 8; kb++) {
        const int cur = kb & 1;
        if (kb < 7) {
            issue_out_loads(smem, cur ^ 1, row0, col0, (kb + 1) * 64, tid);
            CP_COMMIT();
            CP_WAIT1();
        } else {
            CP_WAIT0();
        }
        __syncthreads();

        const uint32_t sb  = sbase + (uint32_t)cur * OB_BUF;
        const uint32_t aH  = sb + OB_AH + (uint32_t)wrow * OB_STRIDE + laneO;
        const uint32_t aL  = sb + OB_AL + (uint32_t)wrow * OB_STRIDE + laneO;
        const uint32_t bH  = sb + OB_BH + laneO;
        const uint32_t bL  = sb + OB_BL + laneO;

        #pragma unroll
        for (int kc = 0; kc < 4; kc++) {
            // A frags: ldmatrix order {r0-7/klo, r0-7/khi, r8-15/klo, r8-15/khi}
            // -> mma A order needs {0, 2, 1, 3}
            uint32_t ta[4], tb[4];
            ldm_x4(ta, aH + kc * 32);
            ldm_x4(tb, aL + kc * 32);
            uint32_t ah[4] = {ta[0], ta[2], ta[1], ta[3]};
            uint32_t al[4] = {tb[0], tb[2], tb[1], tb[3]};

            #pragma unroll
            for (int ntp = 0; ntp < 8; ntp++) {
                uint32_t off = (uint32_t)(ntp * 16) * OB_STRIDE + (uint32_t)kc * 32;
                uint32_t wh[4], wl[4];
                ldm_x4(wh, bH + off);
                ldm_x4(wl, bL + off);
                mma_bf16(y[2 * ntp],     ah, wh[0], wh[1]);
                mma_bf16(y[2 * ntp],     ah, wl[0], wl[1]);
                mma_bf16(y[2 * ntp],     al, wh[0], wh[1]);
                mma_bf16(y[2 * ntp + 1], ah, wh[2], wh[3]);
                mma_bf16(y[2 * ntp + 1], ah, wl[2], wl[3]);
                mma_bf16(y[2 * ntp + 1], al, wh[2], wh[3]);
            }
        }
        __syncthreads();
    }

    // ---- writeback with bias ----
    const int r0 = row0 + wrow + g, r1 = r0 + 8;
    #pragma unroll
    for (int nt = 0; nt < 16; nt++) {
        int col = col0 + nt * 8 + 2 * t4;
        float b0 = bO[col], b1 = bO[col + 1];
        *reinterpret_cast<float2*>(out + (size_t)r0 * DOUT + col) =
            make_float2(y[nt][0] + b0, y[nt][1] + b1);
        *reinterpret_cast<float2*>(out + (size_t)r1 * DOUT + col) =
            make_float2(y[nt][2] + b0, y[nt][3] + b1);
    }
}

// ---------------------------------------------------------------------------
extern "C" void kernel_launch(void* const* d_in, const int* in_sizes, int n_in,
                              void* d_out, int out_size)
{
    const float* z  = (const float*)d_in[0];   // (4,1024,8,64)
    const float* R  = (const float*)d_in[1];   // (8,2048,64)
    const float* q  = (const float*)d_in[2];   // (8,2048)
    const float* W  = (const float*)d_in[3];   // (8,2048,64)
    const float* WO = (const float*)d_in[4];   // (512,512)
    const float* bO = (const float*)d_in[5];   // (512)
    float* out = (float*)d_out;                // (4,1024,512)
    (void)in_sizes; (void)n_in; (void)out_size;

    cudaFuncSetAttribute(fused_mma, cudaFuncAttributeMaxDynamicSharedMemorySize,
                         SMEM_BYTES);
    cudaFuncSetAttribute(out_tc, cudaFuncAttributeMaxDynamicSharedMemorySize,
                         OUT_SMEM);

    prep_land<<<NHEAD * NLAND / 8, 256>>>(R, q);
    prep_w<<<NHEAD * (NLAND / 64), 256>>>(W);
    prep_wo<<<64, 256>>>(WO);

    dim3 gridF(BS_ROWS / 128, NHEAD);          // (32, 8)
    fused_mma<<<gridF, 256, SMEM_BYTES>>>(z);

    dim3 gridO(BS_ROWS / 128, DOUT / 128);     // (32, 4)
    out_tc<<<gridO, 256, OUT_SMEM>>>(bO, out);
}